// round 2
// baseline (speedup 1.0000x reference)
#include <cuda_runtime.h>
#include <math.h>

// Problem constants (fixed by the dataset)
#define NB   8192      // batch rows
#define NV   32000     // vocab (row length)
#define NK   5         // negatives per row
#define NS   100       // sampling-domain columns of prob
#define EPSF 1e-10f

// Scratch: per-row loss contribution (written every call; no init needed)
__device__ float g_row_loss[NB];

// One CTA per row: streaming max over 32000 f32 (8000 float4), then the
// tiny gather/exp/log epilogue on thread 0.
__global__ __launch_bounds__(256) void row_loss_kernel(
    const float* __restrict__ yHat,
    const float* __restrict__ prob,
    const int*   __restrict__ y,
    const int*   __restrict__ ind)
{
    const int b = blockIdx.x;
    const float* __restrict__ rowf = yHat + (long long)b * NV;
    const float4* __restrict__ row4 = reinterpret_cast<const float4*>(rowf);

    // 32000 / 4 = 8000 float4 per row, strided by 256 threads.
    float m = -INFINITY;
    #pragma unroll 4
    for (int i = threadIdx.x; i < NV / 4; i += 256) {
        float4 v = __ldg(&row4[i]);
        m = fmaxf(m, fmaxf(fmaxf(v.x, v.y), fmaxf(v.z, v.w)));
    }

    // warp reduce (max)
    #pragma unroll
    for (int o = 16; o; o >>= 1)
        m = fmaxf(m, __shfl_xor_sync(0xffffffffu, m, o));

    __shared__ float smax[8];
    const int lane = threadIdx.x & 31;
    const int wid  = threadIdx.x >> 5;
    if (lane == 0) smax[wid] = m;
    __syncthreads();

    if (threadIdx.x == 0) {
        float mm = smax[0];
        #pragma unroll
        for (int w = 1; w < 8; ++w) mm = fmaxf(mm, smax[w]);

        const int yb = y[b];
        const float* __restrict__ prow = prob + (long long)yb * NS;

        // Gather target + negatives (row is L2-hot from the streaming pass)
        float t[NK];
        float q = INFINITY;
        #pragma unroll
        for (int j = 0; j < NK; ++j) {
            const int id = ind[b * NK + j];            // index into [0,100)
            const float pj = 1.0f / prow[id];          // importance weight
            q = fminf(q, pj);
            t[j] = pj * expf(rowf[id] - mm);           // complement terms
        }
        const float t0 = q * expf(rowf[yb] - mm);

        float S = t0;
        #pragma unroll
        for (int j = 0; j < NK; ++j) S += t[j];
        const float inv = 1.0f / S;

        // row contribution: log(out0+eps) + sum_j log(1-out_j+eps)
        float acc = logf(t0 * inv + EPSF);
        #pragma unroll
        for (int j = 0; j < NK; ++j)
            acc += logf(1.0f - t[j] * inv + EPSF);

        g_row_loss[b] = acc;
    }
}

// Deterministic sum of the 8192 per-row losses -> mean -> d_out[0]
__global__ __launch_bounds__(1024) void reduce_kernel(float* __restrict__ out)
{
    __shared__ float s[32];
    float v = 0.0f;
    #pragma unroll
    for (int i = threadIdx.x; i < NB; i += 1024) v += g_row_loss[i];

    #pragma unroll
    for (int o = 16; o; o >>= 1) v += __shfl_xor_sync(0xffffffffu, v, o);

    const int lane = threadIdx.x & 31;
    const int wid  = threadIdx.x >> 5;
    if (lane == 0) s[wid] = v;
    __syncthreads();

    if (threadIdx.x < 32) {
        v = s[threadIdx.x];
        #pragma unroll
        for (int o = 16; o; o >>= 1) v += __shfl_xor_sync(0xffffffffu, v, o);
        if (threadIdx.x == 0)
            out[0] = -v / (float)(NB * (NK + 1));   // mean over B*(k+1), negated
    }
}

extern "C" void kernel_launch(void* const* d_in, const int* in_sizes, int n_in,
                              void* d_out, int out_size)
{
    const float* yHat = (const float*)d_in[0];   // [8192, 32000] f32
    const float* prob = (const float*)d_in[1];   // [32000, 100] f32
    const int*   y    = (const int*)d_in[2];     // [8192] i32
    const int*   ind  = (const int*)d_in[3];     // [8192, 5] i32
    float* out = (float*)d_out;

    row_loss_kernel<<<NB, 256>>>(yHat, prob, y, ind);
    reduce_kernel<<<1, 1024>>>(out);
}

// round 4
// speedup vs baseline: 17.6738x; 17.6738x over previous
#include <cuda_runtime.h>
#include <math.h>

// Problem constants (fixed by the dataset)
#define NB   8192      // batch rows
#define NV   32000     // vocab (row length)
#define NK   5         // negatives per row
#define NS   100       // sampling-domain columns of prob
#define EPSF 1e-10f

#define NCTA 32        // 32 CTAs x 256 threads = 8192 = one thread per row

// Scratch for the fused cross-block reduction (no allocs allowed)
__device__ float g_partial[NCTA];
__device__ int   g_ticket = 0;   // re-armed to 0 by the last block each call

// Key insight: the detached row-max shift cancels exactly in the normalized
// ratio out = terms / sum(terms), so the 1 GB streaming max over yHat is
// mathematically unnecessary for the loss VALUE. We compute the loss from
// just the 6 gathered logits per row (indices ind[] are all < 100, plus the
// target column y[b]).
__global__ __launch_bounds__(256) void blackout_fused_kernel(
    const float* __restrict__ yHat,
    const float* __restrict__ prob,
    const int*   __restrict__ y,
    const int*   __restrict__ ind,
    float*       __restrict__ out)
{
    const int b = blockIdx.x * 256 + threadIdx.x;   // 0..8191, exact cover

    // ---- independent index loads (one dependency level) ----
    const int yb = __ldg(&y[b]);
    int id[NK];
    #pragma unroll
    for (int j = 0; j < NK; ++j) id[j] = __ldg(&ind[b * NK + j]);

    // ---- gather level: all 11 loads independent of each other ----
    const float* __restrict__ prow = prob + (long long)yb * NS;
    const float* __restrict__ rowf = yHat + (long long)b * NV;

    float pr[NK], cj[NK];
    #pragma unroll
    for (int j = 0; j < NK; ++j) {
        pr[j] = __ldg(&prow[id[j]]);   // prob[y[b]][ind_j]
        cj[j] = __ldg(&rowf[id[j]]);   // yHat[b][ind_j]  (ind_j < 100)
    }
    const float tg = __ldg(&rowf[yb]); // target logit

    // ---- compute (no max shift needed: it cancels in the ratio) ----
    float p[NK], q = INFINITY;
    #pragma unroll
    for (int j = 0; j < NK; ++j) {
        p[j] = 1.0f / pr[j];
        q = fminf(q, p[j]);
    }

    float t[NK];
    float t0 = q * expf(tg);
    float S  = t0;
    #pragma unroll
    for (int j = 0; j < NK; ++j) {
        t[j] = p[j] * expf(cj[j]);
        S += t[j];
    }
    const float inv = 1.0f / S;

    float acc = logf(t0 * inv + EPSF);          // log(out_0 + eps)
    #pragma unroll
    for (int j = 0; j < NK; ++j)
        acc += logf(1.0f - t[j] * inv + EPSF);  // log(1 - out_j + eps)

    // ---- deterministic block reduction (256 -> 1) ----
    __shared__ float sw[8];
    #pragma unroll
    for (int o = 16; o; o >>= 1) acc += __shfl_xor_sync(0xffffffffu, acc, o);
    const int lane = threadIdx.x & 31;
    const int wid  = threadIdx.x >> 5;
    if (lane == 0) sw[wid] = acc;
    __syncthreads();
    if (threadIdx.x == 0) {
        float v = sw[0];
        #pragma unroll
        for (int w = 1; w < 8; ++w) v += sw[w];
        g_partial[blockIdx.x] = v;
        __threadfence();                         // publish partial to L2
        // ticket: last block to arrive does the final 32-way sum
        int t_ = atomicAdd(&g_ticket, 1);
        sw[0] = (t_ == NCTA - 1) ? 1.0f : 0.0f;
    }
    __syncthreads();

    if (sw[0] != 0.0f && threadIdx.x < 32) {
        // volatile: bypass this SM's (non-coherent) L1 when reading partials
        // produced by other SMs.
        volatile float* gp = g_partial;
        float v = gp[threadIdx.x];               // NCTA == 32 partials, fixed order
        #pragma unroll
        for (int o = 16; o; o >>= 1) v += __shfl_xor_sync(0xffffffffu, v, o);
        if (threadIdx.x == 0) {
            out[0] = -v / (float)(NB * (NK + 1));
            g_ticket = 0;                        // re-arm for the next graph replay
        }
    }
}

extern "C" void kernel_launch(void* const* d_in, const int* in_sizes, int n_in,
                              void* d_out, int out_size)
{
    const float* yHat = (const float*)d_in[0];   // [8192, 32000] f32
    const float* prob = (const float*)d_in[1];   // [32000, 100] f32
    const int*   y    = (const int*)d_in[2];     // [8192] i32
    const int*   ind  = (const int*)d_in[3];     // [8192, 5] i32
    float* out = (float*)d_out;

    blackout_fused_kernel<<<NCTA, 256>>>(yHat, prob, y, ind, out);
}

// round 5
// speedup vs baseline: 18.1287x; 1.0257x over previous
#include <cuda_runtime.h>
#include <math.h>

// Problem constants (fixed by the dataset)
#define NB   8192      // batch rows
#define NV   32000     // vocab (row length)
#define NK   5         // negatives per row
#define NS   100       // sampling-domain columns of prob
#define EPSF 1e-10f

#define NCTA 128       // 128 CTAs x 64 threads = 8192 = one thread per row
#define NTHR 64

// Scratch for the fused cross-block reduction (no allocs allowed)
__device__ float g_partial[NCTA];
__device__ int   g_ticket = 0;   // re-armed to 0 by the last block each call

// The detached row-max shift cancels exactly in out = terms / sum(terms),
// so no streaming pass over yHat is needed — just 6 gathered logits per row
// (ind[] < 100, plus the target column y[b]). Work is pure scattered-load
// latency; grid=128 spreads the L1tex queue pressure over ~128 SMs.
__global__ __launch_bounds__(NTHR) void blackout_fused_kernel(
    const float* __restrict__ yHat,
    const float* __restrict__ prob,
    const int*   __restrict__ y,
    const int*   __restrict__ ind,
    float*       __restrict__ out)
{
    const int b = blockIdx.x * NTHR + threadIdx.x;   // 0..8191, exact cover

    // ---- independent index loads (one dependency level) ----
    const int yb = __ldg(&y[b]);
    int id[NK];
    #pragma unroll
    for (int j = 0; j < NK; ++j) id[j] = __ldg(&ind[b * NK + j]);

    // ---- gather level: all 11 loads independent of each other ----
    const float* __restrict__ prow = prob + (long long)yb * NS;
    const float* __restrict__ rowf = yHat + (long long)b * NV;

    float pr[NK], cj[NK];
    #pragma unroll
    for (int j = 0; j < NK; ++j) {
        pr[j] = __ldg(&prow[id[j]]);   // prob[y[b]][ind_j]
        cj[j] = __ldg(&rowf[id[j]]);   // yHat[b][ind_j]  (ind_j < 100)
    }
    const float tg = __ldg(&rowf[yb]); // target logit

    // ---- compute (no max shift needed: it cancels in the ratio) ----
    float p[NK], q = INFINITY;
    #pragma unroll
    for (int j = 0; j < NK; ++j) {
        p[j] = 1.0f / pr[j];
        q = fminf(q, p[j]);
    }

    float t[NK];
    float t0 = q * expf(tg);
    float S  = t0;
    #pragma unroll
    for (int j = 0; j < NK; ++j) {
        t[j] = p[j] * expf(cj[j]);
        S += t[j];
    }
    const float inv = 1.0f / S;

    float acc = logf(t0 * inv + EPSF);          // log(out_0 + eps)
    #pragma unroll
    for (int j = 0; j < NK; ++j)
        acc += logf(1.0f - t[j] * inv + EPSF);  // log(1 - out_j + eps)

    // ---- deterministic block reduction (64 -> 1) ----
    __shared__ float sw[2];
    #pragma unroll
    for (int o = 16; o; o >>= 1) acc += __shfl_xor_sync(0xffffffffu, acc, o);
    const int lane = threadIdx.x & 31;
    const int wid  = threadIdx.x >> 5;
    if (lane == 0) sw[wid] = acc;
    __syncthreads();

    __shared__ int s_last;
    if (threadIdx.x == 0) {
        g_partial[blockIdx.x] = sw[0] + sw[1];
        __threadfence();                         // publish partial to L2
        // ticket: last block to arrive does the final 128-way sum
        int t_ = atomicAdd(&g_ticket, 1);
        s_last = (t_ == NCTA - 1);
    }
    __syncthreads();

    if (s_last && threadIdx.x < 32) {
        // volatile: bypass this SM's (non-coherent) L1 when reading partials
        // produced by other SMs. Fixed order -> deterministic.
        volatile float* gp = g_partial;
        float v = 0.0f;
        #pragma unroll
        for (int k = 0; k < NCTA / 32; ++k)
            v += gp[k * 32 + threadIdx.x];
        #pragma unroll
        for (int o = 16; o; o >>= 1) v += __shfl_xor_sync(0xffffffffu, v, o);
        if (threadIdx.x == 0) {
            out[0] = -v / (float)(NB * (NK + 1));
            g_ticket = 0;                        // re-arm for the next graph replay
        }
    }
}

extern "C" void kernel_launch(void* const* d_in, const int* in_sizes, int n_in,
                              void* d_out, int out_size)
{
    const float* yHat = (const float*)d_in[0];   // [8192, 32000] f32
    const float* prob = (const float*)d_in[1];   // [32000, 100] f32
    const int*   y    = (const int*)d_in[2];     // [8192] i32
    const int*   ind  = (const int*)d_in[3];     // [8192, 5] i32
    float* out = (float*)d_out;

    blackout_fused_kernel<<<NCTA, NTHR>>>(yHat, prob, y, ind, out);
}